// round 14
// baseline (speedup 1.0000x reference)
#include <cuda_runtime.h>
#include <cuda_fp16.h>
#include <cstdint>

// ---------------- problem constants ----------------
#define D_H   2048
#define T_LEN 4096
#define NROWS 8192
#define G_DIM 2048
#define KW    4
#define FLATC 8192
#define KDIM  2048

// ---------------- tiling ----------------
#define BM 128
#define BN 128
#define BK 64                               // 64 fp16 = 128B per row (SW128 native)
#define KCHUNKS (KDIM / BK)                 // 32
#define NSTAGE 3
#define NTHREADS 128                        // 4 warps, 2x2 grid, warp tile 64x64
#define TILE_BYTES (BM * 128)               // 16384
#define STAGE_BYTES (2 * TILE_BYTES)        // 32768 (A + B)
#define SMEM_TOTAL (NSTAGE * STAGE_BYTES)   // 98304

// ---------------- device scratch: fp16(rne), plain K-major ----------------
__device__ __half g_H  [(size_t)NROWS * G_DIM];
__device__ __half g_xc [(size_t)NROWS * D_H];
__device__ __half g_w1c[(size_t)G_DIM * D_H];
__device__ __half g_w2c[(size_t)FLATC * G_DIM];

__device__ __forceinline__ float silu_f(float v) { return v / (1.0f + __expf(-v)); }

__device__ __forceinline__ void cp_async16(uint32_t dst, const void* src) {
    asm volatile("cp.async.cg.shared.global [%0], [%1], 16;" :: "r"(dst), "l"(src));
}
__device__ __forceinline__ uint32_t smem_u32(const void* p) {
    uint32_t a;
    asm("{ .reg .u64 t; cvta.to.shared.u64 t, %1; cvt.u32.u64 %0, t; }" : "=r"(a) : "l"(p));
    return a;
}
__device__ __forceinline__ void ldmatrix_x4(uint32_t addr, uint32_t& r0, uint32_t& r1,
                                            uint32_t& r2, uint32_t& r3) {
    asm volatile("ldmatrix.sync.aligned.m8n8.x4.shared.b16 {%0,%1,%2,%3}, [%4];"
                 : "=r"(r0), "=r"(r1), "=r"(r2), "=r"(r3) : "r"(addr));
}
__device__ __forceinline__ void mma_f16(float c[4], uint32_t a0, uint32_t a1,
                                        uint32_t a2, uint32_t a3,
                                        uint32_t b0, uint32_t b1) {
    asm volatile(
        "mma.sync.aligned.m16n8k16.row.col.f32.f16.f16.f32 "
        "{%0,%1,%2,%3}, {%4,%5,%6,%7}, {%8,%9}, {%0,%1,%2,%3};"
        : "+f"(c[0]), "+f"(c[1]), "+f"(c[2]), "+f"(c[3])
        : "r"(a0), "r"(a1), "r"(a2), "r"(a3), "r"(b0), "r"(b1));
}

// ---------------- pre-convert: fp32 -> fp16(rne), plain layout ----------------
template <int WHICH>
__global__ __launch_bounds__(256)
void cvt_kernel(const float* __restrict__ src, int n8) {
    __half* dst = (WHICH == 0) ? g_xc : (WHICH == 1) ? g_w1c : g_w2c;
    int i = blockIdx.x * 256 + threadIdx.x;
    if (i < n8) {
        const float4* s = (const float4*)src + i * 2;
        float4 lo = s[0], hi = s[1];
        __half2 h[4];
        h[0] = __floats2half2_rn(lo.x, lo.y);
        h[1] = __floats2half2_rn(lo.z, lo.w);
        h[2] = __floats2half2_rn(hi.x, hi.y);
        h[3] = __floats2half2_rn(hi.z, hi.w);
        *(uint4*)(dst + (size_t)i * 8) = *(const uint4*)h;
    }
}

// ---------------- tile loader (SW128 swizzle: chunk c -> c ^ (r&7)) ----------
__device__ __forceinline__ void load_chunk(const __half* __restrict__ A,
                                           const __half* __restrict__ B,
                                           uint32_t stagebase, int k0,
                                           int row0, int col0, int tid) {
#pragma unroll
    for (int j = 0; j < 8; j++) {
        int idx = tid + NTHREADS * j;
        int r = idx >> 3, c = idx & 7;
        cp_async16(stagebase + r * 128 + (c ^ (r & 7)) * 16,
                   A + (size_t)(row0 + r) * KDIM + k0 + c * 8);
    }
#pragma unroll
    for (int j = 0; j < 8; j++) {
        int idx = tid + NTHREADS * j;
        int r = idx >> 3, c = idx & 7;
        cp_async16(stagebase + TILE_BYTES + r * 128 + (c ^ (r & 7)) * 16,
                   B + (size_t)(col0 + r) * KDIM + k0 + c * 8);
    }
}

// ---------------- main GEMM: C[128x128] = A[128x2048] * B[128x2048]^T ----------
// 4 warps, warp tile 64x64 (2x2 warp grid) -> smem read amplification 2x+2x.
template <int EPI>
__global__ __launch_bounds__(NTHREADS, 2)
void gemm_mma(const float* __restrict__ X,
              const float* __restrict__ b2,
              float* __restrict__ out) {
    const __half* A = (EPI == 0) ? (const __half*)g_xc : (const __half*)g_H;
    const __half* B = (EPI == 0) ? (const __half*)g_w1c : (const __half*)g_w2c;

    extern __shared__ char smem[];
    const uint32_t sb = smem_u32(smem);
    const int tid  = threadIdx.x;
    const int lane = tid & 31;
    const int warp = tid >> 5;
    const int wm = warp & 1;            // 0..1 (64-row half)
    const int wn = warp >> 1;           // 0..1 (64-col half)
    const int row0 = blockIdx.y * BM;
    const int col0 = blockIdx.x * BN;
    const int rq = lane >> 2;
    const int kq = lane & 3;

    // ldmatrix per-lane address constants (same mapping as proven rounds 9-12)
    const int l7 = lane & 7;
    const uint32_t cbA = lane >> 4;                 // A chunk bit
    uint32_t aRowOff[4], aSw[4];
#pragma unroll
    for (int mt = 0; mt < 4; mt++) {
        uint32_t r = wm * 64 + mt * 16 + l7 + ((lane >> 3) & 1) * 8;
        aRowOff[mt] = r * 128;
        aSw[mt] = r & 7;
    }
    const uint32_t cbB = (lane >> 3) & 1;           // B chunk bit
    uint32_t bRowOff[4], bSw[4];
#pragma unroll
    for (int g = 0; g < 4; g++) {
        uint32_t r = wn * 64 + (2 * g + ((lane >> 4) & 1)) * 8 + l7;
        bRowOff[g] = r * 128;
        bSw[g] = r & 7;
    }

    float acc[4][8][4];
#pragma unroll
    for (int i = 0; i < 4; i++)
#pragma unroll
        for (int j = 0; j < 8; j++)
#pragma unroll
            for (int k = 0; k < 4; k++) acc[i][j][k] = 0.0f;

    // prologue: chunks 0,1 -> stages 0,1
    load_chunk(A, B, sb, 0, row0, col0, tid);
    asm volatile("cp.async.commit_group;" ::: "memory");
    load_chunk(A, B, sb + STAGE_BYTES, BK, row0, col0, tid);
    asm volatile("cp.async.commit_group;" ::: "memory");

    uint32_t stage = 0;
    for (int i = 0; i < KCHUNKS; i++) {
        if (i + 1 < KCHUNKS) asm volatile("cp.async.wait_group 1;" ::: "memory");
        else                 asm volatile("cp.async.wait_group 0;" ::: "memory");
        __syncthreads();

        if (i + 2 < KCHUNKS) {
            uint32_t ns = stage + 2; if (ns >= NSTAGE) ns -= NSTAGE;
            load_chunk(A, B, sb + ns * STAGE_BYTES, (i + 2) * BK, row0, col0, tid);
            asm volatile("cp.async.commit_group;" ::: "memory");
        }

        const uint32_t aBase = sb + stage * STAGE_BYTES;
        const uint32_t bBase = aBase + TILE_BYTES;

#pragma unroll
        for (int s = 0; s < 4; s++) {
            uint32_t a[4][4];
#pragma unroll
            for (int mt = 0; mt < 4; mt++)
                ldmatrix_x4(aBase + aRowOff[mt] + (((2 * s + cbA) ^ aSw[mt]) << 4),
                            a[mt][0], a[mt][1], a[mt][2], a[mt][3]);
#pragma unroll
            for (int g = 0; g < 4; g++) {
                uint32_t b0, b1, b2_, b3;
                ldmatrix_x4(bBase + bRowOff[g] + (((2 * s + cbB) ^ bSw[g]) << 4),
                            b0, b1, b2_, b3);
#pragma unroll
                for (int mt = 0; mt < 4; mt++) {
                    mma_f16(acc[mt][2 * g],     a[mt][0], a[mt][1], a[mt][2], a[mt][3], b0, b1);
                    mma_f16(acc[mt][2 * g + 1], a[mt][0], a[mt][1], a[mt][2], a[mt][3], b2_, b3);
                }
            }
        }
        stage = stage + 1; if (stage >= NSTAGE) stage -= NSTAGE;
    }

    // ---------------- epilogue ----------------
    const int q = kq;

    if (EPI == 0) {
        // silu -> g_H (fp16, plain K-major)
#pragma unroll
        for (int mt = 0; mt < 4; mt++) {
            int n = row0 + wm * 64 + mt * 16 + rq;
#pragma unroll
            for (int nt = 0; nt < 8; nt++) {
                int g = col0 + wn * 64 + nt * 8 + 2 * q;
                __half2 v0 = __floats2half2_rn(silu_f(acc[mt][nt][0]), silu_f(acc[mt][nt][1]));
                __half2 v1 = __floats2half2_rn(silu_f(acc[mt][nt][2]), silu_f(acc[mt][nt][3]));
                *(__half2*)(g_H + (size_t)n * G_DIM + g) = v0;
                *(__half2*)(g_H + (size_t)(n + 8) * G_DIM + g) = v1;
            }
        }
    } else {
        // bias + causal depthwise conv + silu -> out (verified since round 3)
        const int halfd = q >> 1;
        const int wa = (q & 1) * 2;
#pragma unroll
        for (int nt = 0; nt < 8; nt++) {
            const int cb = col0 + wn * 64 + nt * 8;
            const int d  = (cb >> 2) + halfd;
            const float bias0 = b2[cb + 2 * q];
            const float bias1 = b2[cb + 2 * q + 1];
#pragma unroll
            for (int mt = 0; mt < 4; mt++) {
#pragma unroll
                for (int h = 0; h < 2; h++) {
                    const int n = row0 + wm * 64 + mt * 16 + rq + h * 8;
                    const int bb = n >> 12;
                    const int t  = n & (T_LEN - 1);
                    const float k0 = acc[mt][nt][2 * h + 0] + bias0;
                    const float k1 = acc[mt][nt][2 * h + 1] + bias1;
                    const float* xb = X + (size_t)bb * T_LEN * D_H + d;
                    float partial = 0.0f;
                    const int tt0 = t - (KW - 1) + wa;
                    if (tt0 >= 0)     partial = fmaf(xb[(size_t)tt0 * D_H], k0, partial);
                    if (tt0 + 1 >= 0) partial = fmaf(xb[(size_t)(tt0 + 1) * D_H], k1, partial);
                    const float tot = partial + __shfl_xor_sync(0xffffffffu, partial, 1);
                    if ((q & 1) == 0)
                        out[(size_t)n * D_H + d] = silu_f(tot);
                }
            }
        }
    }
}

// ---------------------------------------------------------------------------
extern "C" void kernel_launch(void* const* d_in, const int* in_sizes, int n_in,
                              void* d_out, int out_size) {
    const float* x  = (const float*)d_in[0];
    const float* w1 = (const float*)d_in[1];
    const float* w2 = (const float*)d_in[2];
    const float* b2 = (const float*)d_in[3];
    float* out = (float*)d_out;

    cudaFuncSetAttribute(gemm_mma<0>, cudaFuncAttributeMaxDynamicSharedMemorySize, SMEM_TOTAL);
    cudaFuncSetAttribute(gemm_mma<1>, cudaFuncAttributeMaxDynamicSharedMemorySize, SMEM_TOTAL);

    cvt_kernel<0><<<(NROWS * D_H / 8 + 255) / 256, 256>>>(x,  NROWS * D_H / 8);
    cvt_kernel<1><<<(G_DIM * D_H / 8 + 255) / 256, 256>>>(w1, G_DIM * D_H / 8);
    cvt_kernel<2><<<(FLATC * G_DIM / 8 + 255) / 256, 256>>>(w2, FLATC * G_DIM / 8);

    dim3 blk(NTHREADS);
    dim3 g1(G_DIM / BN, NROWS / BM);    // (16, 64)
    gemm_mma<0><<<g1, blk, SMEM_TOTAL>>>(nullptr, nullptr, nullptr);

    dim3 g2(FLATC / BN, NROWS / BM);    // (64, 64)
    gemm_mma<1><<<g2, blk, SMEM_TOTAL>>>(x, b2, out);
}

// round 15
// speedup vs baseline: 1.1353x; 1.1353x over previous
#include <cuda_runtime.h>
#include <cuda_fp16.h>
#include <cstdint>

// ---------------- problem constants ----------------
#define D_H   2048
#define T_LEN 4096
#define NROWS 8192
#define G_DIM 2048
#define KW    4
#define FLATC 8192
#define KDIM  2048

// ---------------- tiling ----------------
#define BM 128
#define BN 128
#define BK 64                               // 64 fp16 = 128B per row (SW128 native)
#define KCHUNKS (KDIM / BK)                 // 32
#define NSTAGE 3
#define TILE_BYTES (BM * 128)               // 16384
#define STAGE_BYTES (2 * TILE_BYTES)        // 32768 (A + B)
#define SMEM_TOTAL (NSTAGE * STAGE_BYTES)   // 98304

// ---------------- device scratch: fp16(rne), plain K-major ----------------
__device__ __half g_H  [(size_t)NROWS * G_DIM];
__device__ __half g_xc [(size_t)NROWS * D_H];
__device__ __half g_w1c[(size_t)G_DIM * D_H];
__device__ __half g_w2c[(size_t)FLATC * G_DIM];

__device__ __forceinline__ float silu_f(float v) { return v / (1.0f + __expf(-v)); }

__device__ __forceinline__ void cp_async16(uint32_t dst, const void* src) {
    asm volatile("cp.async.cg.shared.global [%0], [%1], 16;" :: "r"(dst), "l"(src));
}
__device__ __forceinline__ uint32_t smem_u32(const void* p) {
    uint32_t a;
    asm("{ .reg .u64 t; cvta.to.shared.u64 t, %1; cvt.u32.u64 %0, t; }" : "=r"(a) : "l"(p));
    return a;
}
__device__ __forceinline__ void ldmatrix_x4(uint32_t addr, uint32_t& r0, uint32_t& r1,
                                            uint32_t& r2, uint32_t& r3) {
    asm volatile("ldmatrix.sync.aligned.m8n8.x4.shared.b16 {%0,%1,%2,%3}, [%4];"
                 : "=r"(r0), "=r"(r1), "=r"(r2), "=r"(r3) : "r"(addr));
}
__device__ __forceinline__ void mma_f16(float c[4], uint32_t a0, uint32_t a1,
                                        uint32_t a2, uint32_t a3,
                                        uint32_t b0, uint32_t b1) {
    asm volatile(
        "mma.sync.aligned.m16n8k16.row.col.f32.f16.f16.f32 "
        "{%0,%1,%2,%3}, {%4,%5,%6,%7}, {%8,%9}, {%0,%1,%2,%3};"
        : "+f"(c[0]), "+f"(c[1]), "+f"(c[2]), "+f"(c[3])
        : "r"(a0), "r"(a1), "r"(a2), "r"(a3), "r"(b0), "r"(b1));
}

// ---------------- pre-convert: fp32 -> fp16(rne), plain layout ----------------
template <int WHICH>
__global__ __launch_bounds__(256)
void cvt_kernel(const float* __restrict__ src, int n8) {
    __half* dst = (WHICH == 0) ? g_xc : (WHICH == 1) ? g_w1c : g_w2c;
    int i = blockIdx.x * 256 + threadIdx.x;
    if (i < n8) {
        const float4* s = (const float4*)src + i * 2;
        float4 lo = s[0], hi = s[1];
        __half2 h[4];
        h[0] = __floats2half2_rn(lo.x, lo.y);
        h[1] = __floats2half2_rn(lo.z, lo.w);
        h[2] = __floats2half2_rn(hi.x, hi.y);
        h[3] = __floats2half2_rn(hi.z, hi.w);
        *(uint4*)(dst + (size_t)i * 8) = *(const uint4*)h;
    }
}

// ---------------- one slice (32 A rows + 32 B rows) of a chunk -------------
// slice j in 0..3; per-thread 1 A cp.async + 1 B cp.async.
__device__ __forceinline__ void load_slice(const __half* __restrict__ A,
                                           const __half* __restrict__ B,
                                           uint32_t stagebase, int k0,
                                           int row0, int col0, int tid, int j) {
    int idx = tid + 256 * j;
    int r = idx >> 3, c = idx & 7;
    uint32_t soff = r * 128 + ((c ^ (r & 7)) << 4);
    cp_async16(stagebase + soff, A + (size_t)(row0 + r) * KDIM + k0 + c * 8);
    cp_async16(stagebase + TILE_BYTES + soff, B + (size_t)(col0 + r) * KDIM + k0 + c * 8);
}

// ---------------- main GEMM: C[128x128] = A[128x2048] * B[128x2048]^T ----------
template <int EPI>
__global__ __launch_bounds__(256, 2)
void gemm_mma(const float* __restrict__ X,
              const float* __restrict__ b2,
              float* __restrict__ out) {
    const __half* A = (EPI == 0) ? (const __half*)g_xc : (const __half*)g_H;
    const __half* B = (EPI == 0) ? (const __half*)g_w1c : (const __half*)g_w2c;

    extern __shared__ char smem[];
    const uint32_t sb = smem_u32(smem);
    const int tid  = threadIdx.x;
    const int lane = tid & 31;
    const int warp = tid >> 5;
    const int wm = warp & 3;
    const int wn = warp >> 2;
    const int row0 = blockIdx.y * BM;
    const int col0 = blockIdx.x * BN;
    const int rq = lane >> 2;
    const int kq = lane & 3;

    // ldmatrix per-lane address constants (mapping proven rounds 9-12)
    const int l7 = lane & 7;
    const uint32_t cbA = lane >> 4;
    uint32_t aRowOff[2], aSw[2];
#pragma unroll
    for (int mt = 0; mt < 2; mt++) {
        uint32_t r = wm * 32 + mt * 16 + l7 + ((lane >> 3) & 1) * 8;
        aRowOff[mt] = r * 128;
        aSw[mt] = r & 7;
    }
    const uint32_t cbB = (lane >> 3) & 1;
    uint32_t bRowOff[4], bSw[4];
#pragma unroll
    for (int g = 0; g < 4; g++) {
        uint32_t r = wn * 64 + (2 * g + ((lane >> 4) & 1)) * 8 + l7;
        bRowOff[g] = r * 128;
        bSw[g] = r & 7;
    }

    float acc[2][8][4];
#pragma unroll
    for (int i = 0; i < 2; i++)
#pragma unroll
        for (int j = 0; j < 8; j++)
#pragma unroll
            for (int k = 0; k < 4; k++) acc[i][j][k] = 0.0f;

    // prologue: chunks 0,1 -> stages 0,1
#pragma unroll
    for (int j = 0; j < 4; j++) load_slice(A, B, sb, 0, row0, col0, tid, j);
    asm volatile("cp.async.commit_group;" ::: "memory");
#pragma unroll
    for (int j = 0; j < 4; j++) load_slice(A, B, sb + STAGE_BYTES, BK, row0, col0, tid, j);
    asm volatile("cp.async.commit_group;" ::: "memory");

    uint32_t stage = 0;
    for (int i = 0; i < KCHUNKS; i++) {
        if (i + 1 < KCHUNKS) asm volatile("cp.async.wait_group 1;" ::: "memory");
        else                 asm volatile("cp.async.wait_group 0;" ::: "memory");
        __syncthreads();

        const bool pf = (i + 2 < KCHUNKS);
        uint32_t ns = stage + 2; if (ns >= NSTAGE) ns -= NSTAGE;
        const uint32_t nsBase = sb + ns * STAGE_BYTES;
        const int nk0 = (i + 2) * BK;

        const uint32_t aBase = sb + stage * STAGE_BYTES;
        const uint32_t bBase = aBase + TILE_BYTES;

        // k-steps with cp.async issue spread across them (1 slice per k-step)
#pragma unroll
        for (int s = 0; s < 4; s++) {
            if (pf) load_slice(A, B, nsBase, nk0, row0, col0, tid, s);

            uint32_t a[2][4];
#pragma unroll
            for (int mt = 0; mt < 2; mt++)
                ldmatrix_x4(aBase + aRowOff[mt] + (((2 * s + cbA) ^ aSw[mt]) << 4),
                            a[mt][0], a[mt][1], a[mt][2], a[mt][3]);
#pragma unroll
            for (int g = 0; g < 4; g++) {
                uint32_t b0, b1, b2_, b3;
                ldmatrix_x4(bBase + bRowOff[g] + (((2 * s + cbB) ^ bSw[g]) << 4),
                            b0, b1, b2_, b3);
#pragma unroll
                for (int mt = 0; mt < 2; mt++) {
                    mma_f16(acc[mt][2 * g],     a[mt][0], a[mt][1], a[mt][2], a[mt][3], b0, b1);
                    mma_f16(acc[mt][2 * g + 1], a[mt][0], a[mt][1], a[mt][2], a[mt][3], b2_, b3);
                }
            }
        }
        if (pf) asm volatile("cp.async.commit_group;" ::: "memory");
        stage = stage + 1; if (stage >= NSTAGE) stage -= NSTAGE;
    }

    // ---------------- epilogue ----------------
    const int q = kq;

    if (EPI == 0) {
        // silu -> g_H (fp16, plain K-major)
#pragma unroll
        for (int mt = 0; mt < 2; mt++) {
            int n = row0 + wm * 32 + mt * 16 + rq;
#pragma unroll
            for (int nt = 0; nt < 8; nt++) {
                int g = col0 + wn * 64 + nt * 8 + 2 * q;
                __half2 v0 = __floats2half2_rn(silu_f(acc[mt][nt][0]), silu_f(acc[mt][nt][1]));
                __half2 v1 = __floats2half2_rn(silu_f(acc[mt][nt][2]), silu_f(acc[mt][nt][3]));
                *(__half2*)(g_H + (size_t)n * G_DIM + g) = v0;
                *(__half2*)(g_H + (size_t)(n + 8) * G_DIM + g) = v1;
            }
        }
    } else {
        // bias + causal depthwise conv + silu -> out (verified since round 3)
        const int halfd = q >> 1;
        const int wa = (q & 1) * 2;
#pragma unroll
        for (int nt = 0; nt < 8; nt++) {
            const int cb = col0 + wn * 64 + nt * 8;
            const int d  = (cb >> 2) + halfd;
            const float bias0 = b2[cb + 2 * q];
            const float bias1 = b2[cb + 2 * q + 1];
#pragma unroll
            for (int mt = 0; mt < 2; mt++) {
#pragma unroll
                for (int h = 0; h < 2; h++) {
                    const int n = row0 + wm * 32 + mt * 16 + rq + h * 8;
                    const int bb = n >> 12;
                    const int t  = n & (T_LEN - 1);
                    const float k0 = acc[mt][nt][2 * h + 0] + bias0;
                    const float k1 = acc[mt][nt][2 * h + 1] + bias1;
                    const float* xb = X + (size_t)bb * T_LEN * D_H + d;
                    float partial = 0.0f;
                    const int tt0 = t - (KW - 1) + wa;
                    if (tt0 >= 0)     partial = fmaf(xb[(size_t)tt0 * D_H], k0, partial);
                    if (tt0 + 1 >= 0) partial = fmaf(xb[(size_t)(tt0 + 1) * D_H], k1, partial);
                    const float tot = partial + __shfl_xor_sync(0xffffffffu, partial, 1);
                    if ((q & 1) == 0)
                        out[(size_t)n * D_H + d] = silu_f(tot);
                }
            }
        }
    }
}

// ---------------------------------------------------------------------------
extern "C" void kernel_launch(void* const* d_in, const int* in_sizes, int n_in,
                              void* d_out, int out_size) {
    const float* x  = (const float*)d_in[0];
    const float* w1 = (const float*)d_in[1];
    const float* w2 = (const float*)d_in[2];
    const float* b2 = (const float*)d_in[3];
    float* out = (float*)d_out;

    cudaFuncSetAttribute(gemm_mma<0>, cudaFuncAttributeMaxDynamicSharedMemorySize, SMEM_TOTAL);
    cudaFuncSetAttribute(gemm_mma<1>, cudaFuncAttributeMaxDynamicSharedMemorySize, SMEM_TOTAL);

    cvt_kernel<0><<<(NROWS * D_H / 8 + 255) / 256, 256>>>(x,  NROWS * D_H / 8);
    cvt_kernel<1><<<(G_DIM * D_H / 8 + 255) / 256, 256>>>(w1, G_DIM * D_H / 8);
    cvt_kernel<2><<<(FLATC * G_DIM / 8 + 255) / 256, 256>>>(w2, FLATC * G_DIM / 8);

    dim3 blk(256);
    dim3 g1(G_DIM / BN, NROWS / BM);    // (16, 64)
    gemm_mma<0><<<g1, blk, SMEM_TOTAL>>>(nullptr, nullptr, nullptr);

    dim3 g2(FLATC / BN, NROWS / BM);    // (64, 64)
    gemm_mma<1><<<g2, blk, SMEM_TOTAL>>>(x, b2, out);
}